// round 14
// baseline (speedup 1.0000x reference)
#include <cuda_runtime.h>
#include <cuda_fp16.h>
#include <math.h>
#include <stdint.h>

#define BATCH   16384
#define LATENT  64
#define HID     512
#define OUTD    256
#define KEXP    (HID * 9)    // 4608 = [silu 512 | bases 4096]
#define NSUP_L  (KEXP / 128) // 36 super-chunks of 128 halves

// ---------------- scratch (device globals; allocation-free rule) ------------
__device__ __half g_phi1[(size_t)BATCH * KEXP];
__device__ __half g_phi2[(size_t)BATCH * KEXP];
__device__ __half g_xh [(size_t)BATCH * LATENT];
__device__ __half g_Wdh[(size_t)HID * LATENT];
__device__ __half g_W1 [(size_t)HID  * KEXP];
__device__ __half g_W2 [(size_t)OUTD * KEXP];

// ---------------- helpers -----------------------------------------------------
__device__ __forceinline__ uint32_t smem_u32(const void* p) {
    uint32_t a;
    asm("{ .reg .u64 t; cvta.to.shared.u64 t, %1; cvt.u32.u64 %0, t; }" : "=r"(a) : "l"(p));
    return a;
}
__device__ __forceinline__ void cp16(uint32_t dst, const void* src) {
    asm volatile("cp.async.cg.shared.global [%0], [%1], 16;" :: "r"(dst), "l"(src));
}
__device__ __forceinline__ void ldm_x4(uint32_t* r, uint32_t addr) {
    asm volatile("ldmatrix.sync.aligned.m8n8.x4.shared.b16 {%0,%1,%2,%3}, [%4];"
        : "=r"(r[0]), "=r"(r[1]), "=r"(r[2]), "=r"(r[3]) : "r"(addr));
}
__device__ __forceinline__ void mma_f16(float* d, const uint32_t* a, uint32_t b0, uint32_t b1) {
    asm volatile(
        "mma.sync.aligned.m16n8k16.row.col.f32.f16.f16.f32 "
        "{%0,%1,%2,%3}, {%4,%5,%6,%7}, {%8,%9}, {%0,%1,%2,%3};"
        : "+f"(d[0]), "+f"(d[1]), "+f"(d[2]), "+f"(d[3])
        : "r"(a[0]), "r"(a[1]), "r"(a[2]), "r"(a[3]), "r"(b0), "r"(b1));
}

// division-free Cox-de Boor cubic bases -> 8 fp16 packed in uint4
__device__ __forceinline__ uint4 bases8_h(float xv) {
    float g[12];
#pragma unroll
    for (int j = 0; j < 12; j++)
        g[j] = __fadd_rn(__fmul_rn((float)(j - 3), 0.4f), -1.0f);
    float bas[11];
#pragma unroll
    for (int j = 0; j < 11; j++)
        bas[j] = (xv >= g[j] && xv < g[j + 1]) ? 1.0f : 0.0f;
    const float rcp[3] = {2.5f, 1.25f, (float)(1.0 / 1.2)};
#pragma unroll
    for (int k = 1; k <= 3; k++) {
        float r = rcp[k - 1];
#pragma unroll
        for (int j = 0; j < 11 - k; j++) {
            float left  = (xv - g[j])         * r * bas[j];
            float right = (g[j + k + 1] - xv) * r * bas[j + 1];
            bas[j] = left + right;
        }
    }
    __half hb[8];
#pragma unroll
    for (int j = 0; j < 8; j++) hb[j] = __float2half_rn(bas[j]);
    return *(uint4*)hb;
}

// write phi row entries for two adjacent h values (col even)
__device__ __forceinline__ void expand_store(__half* __restrict__ phi,
                                             int row, int col, float v0, float v1) {
    float s0 = v0 / (1.0f + expf(-v0));
    float s1 = v1 / (1.0f + expf(-v1));
    __half* base = phi + (size_t)row * KEXP;
    *(__half2*)(base + col) = __floats2half2_rn(s0, s1);
    uint4 b0 = bases8_h(v0);
    uint4 b1 = bases8_h(v1);
    *(uint4*)(base + HID + col * 8)     = b0;
    *(uint4*)(base + HID + col * 8 + 8) = b1;
}

// ---------------- merged prep kernel ------------------------------------------
#define N_XH   (BATCH * LATENT)
#define N_WDH  (HID * LATENT)
#define N_W1   (HID * HID)
#define N_W2   (OUTD * HID)
#define N_PREP (N_XH + N_WDH + N_W1 + N_W2)

__global__ void prep_all(const float* __restrict__ x, const float* __restrict__ dw,
                         const float* __restrict__ bw1, const float* __restrict__ sw1,
                         const float* __restrict__ sc1,
                         const float* __restrict__ bw2, const float* __restrict__ sw2,
                         const float* __restrict__ sc2,
                         __half* __restrict__ xh, __half* __restrict__ Wdh,
                         __half* __restrict__ W1, __half* __restrict__ W2) {
    int u = blockIdx.x * blockDim.x + threadIdx.x;
    if (u < N_XH) { xh[u] = __float2half_rn(x[u]); return; }
    u -= N_XH;
    if (u < N_WDH) { Wdh[u] = __float2half_rn(dw[u]); return; }
    u -= N_WDH;
    const float* bw; const float* sw; const float* sc; __half* Wt;
    if (u < N_W1) { bw = bw1; sw = sw1; sc = sc1; Wt = W1; }
    else { u -= N_W1; if (u >= N_W2) return; bw = bw2; sw = sw2; sc = sc2; Wt = W2; }
    int o = u / HID, i = u % HID;
    float s = sc[(size_t)o * HID + i];
    Wt[(size_t)o * KEXP + i] = __float2half_rn(bw[(size_t)o * HID + i]);
    size_t base = (size_t)o * KEXP + HID + (size_t)i * 8;
#pragma unroll
    for (int g = 0; g < 8; g++)
        Wt[base + g] = __float2half_rn(sw[((size_t)o * HID + i) * 8 + g] * s);
}

// ---------------- prelude GEMM (K=64): epilogue emits phi1 --------------------
#define PITCHW  36
#define DA_W    (128 * PITCHW)
#define DB_W    (256 * PITCHW)
#define DSMEM_BYTES ((DA_W + DB_W) * 4)

__global__ __launch_bounds__(512, 1) void gemm_pre(
    const __half* __restrict__ A, const __half* __restrict__ W,
    const float* __restrict__ bias, __half* __restrict__ phid, int N)
{
    constexpr int K = LATENT;
    extern __shared__ __align__(16) uint32_t smu[];
    const uint32_t sbase = smem_u32(smu);
    const int tid = threadIdx.x;
    const int wid = tid >> 5, lane = tid & 31;
    const int wm = wid & 3, wn = wid >> 2;
    const int bm = blockIdx.y * 128, bn = blockIdx.x * 256;

    const uint32_t laneRow = lane & 15, laneKB = (lane >> 4) * 16;
    const uint32_t aLaneOff = (wm * 32 + laneRow) * (PITCHW * 4) + laneKB;
    const uint32_t bLaneOff = DA_W * 4 + (wn * 64 + laneRow) * (PITCHW * 4) + laneKB;

    {
        int v0 = tid, v1 = tid + 512;
        int r0 = v0 >> 3, c0 = (v0 & 7) << 3;
        int r1 = v1 >> 3, c1 = (v1 & 7) << 3;
        cp16(sbase + (r0 * PITCHW + (c0 >> 1)) * 4, A + (size_t)(bm + r0) * K + c0);
        cp16(sbase + (r1 * PITCHW + (c1 >> 1)) * 4, A + (size_t)(bm + r1) * K + c1);
#pragma unroll
        for (int i = 0; i < 4; i++) {
            int v = tid + i * 512;
            int r = v >> 3, c = (v & 7) << 3;
            cp16(sbase + (DA_W + r * PITCHW + (c >> 1)) * 4, W + (size_t)(bn + r) * K + c);
        }
        asm volatile("cp.async.commit_group;");
        asm volatile("cp.async.wait_group 0;");
        __syncthreads();
    }

    float acc[2][8][4];
#pragma unroll
    for (int mt = 0; mt < 2; mt++)
#pragma unroll
        for (int nt = 0; nt < 8; nt++)
#pragma unroll
            for (int i = 0; i < 4; i++) acc[mt][nt][i] = 0.0f;

#pragma unroll
    for (int kt = 0; kt < 4; kt++) {
        uint32_t a[2][4], b[4][4];
        ldm_x4(a[0], sbase + aLaneOff + kt * 32);
        ldm_x4(a[1], sbase + aLaneOff + 16 * PITCHW * 4 + kt * 32);
#pragma unroll
        for (int p = 0; p < 4; p++)
            ldm_x4(b[p], sbase + bLaneOff + p * 16 * PITCHW * 4 + kt * 32);
#pragma unroll
        for (int p = 0; p < 4; p++) {
            mma_f16(acc[0][2 * p],     a[0], b[p][0], b[p][2]);
            mma_f16(acc[1][2 * p],     a[1], b[p][0], b[p][2]);
            mma_f16(acc[0][2 * p + 1], a[0], b[p][1], b[p][3]);
            mma_f16(acc[1][2 * p + 1], a[1], b[p][1], b[p][3]);
        }
    }

    const int g = lane >> 2, t = lane & 3;
#pragma unroll
    for (int mt = 0; mt < 2; mt++) {
        int row0 = bm + wm * 32 + mt * 16 + g;
#pragma unroll
        for (int nt = 0; nt < 8; nt++) {
            int col = bn + wn * 64 + nt * 8 + 2 * t;
#pragma unroll
            for (int hrow = 0; hrow < 2; hrow++) {
                int row = row0 + 8 * hrow;
                float v0 = acc[mt][nt][2 * hrow + 0] + bias[col];
                float v1 = acc[mt][nt][2 * hrow + 1] + bias[col + 1];
                v0 = v0 / (1.0f + expf(-v0));    // h0 = silu(pre)
                v1 = v1 / (1.0f + expf(-v1));
                expand_store(phid, row, col, v0, v1);
            }
        }
    }
}

// ---------------- main GEMM: 1024 threads, 32 warps, warp tile 32x32 ----------
// EPI 0: plain float store to C.  EPI 1: expand-store h into phid.
#define SPITCH  68
#define SA_W    (128 * SPITCH)
#define SB_W    (256 * SPITCH)
#define SBUF_W  (SA_W + SB_W)              // 26112 words
#define SSMEM_BYTES (2 * SBUF_W * 4)       // 208896

template <int NSUP, int EPI>
__global__ __launch_bounds__(1024, 1) void gemm_sup(
    const __half* __restrict__ A, const __half* __restrict__ W,
    float* __restrict__ C, __half* __restrict__ phid, int N)
{
    constexpr int K = NSUP * 128;
    extern __shared__ __align__(16) uint32_t smu[];
    const uint32_t sbase = smem_u32(smu);

    const int tid  = threadIdx.x;
    const int wid  = tid >> 5, lane = tid & 31;
    const int wm   = wid & 3;
    const int wn   = wid >> 2;
    const int bm   = blockIdx.y * 128;
    const int bn   = blockIdx.x * 256;

    const uint32_t laneRow = lane & 15;
    const uint32_t laneKB  = (lane >> 4) * 16;
    const uint32_t aLaneOff = (wm * 32 + laneRow) * (SPITCH * 4) + laneKB;
    const uint32_t bLaneOff = SA_W * 4 + (wn * 32 + laneRow) * (SPITCH * 4) + laneKB;

    uint32_t aOff[2], aDst[2], bOff[4], bDst[4];
#pragma unroll
    for (int i = 0; i < 2; i++) {
        int v = tid + i * 1024;
        int r = v >> 4, c = (v & 15) << 3;
        aOff[i] = (uint32_t)((bm + r) * K + c);
        aDst[i] = (r * SPITCH + (c >> 1)) * 4;
    }
#pragma unroll
    for (int i = 0; i < 4; i++) {
        int v = tid + i * 1024;
        int r = v >> 4, c = (v & 15) << 3;
        bOff[i] = (uint32_t)((bn + r) * K + c);
        bDst[i] = (SA_W + r * SPITCH + (c >> 1)) * 4;
    }

    float acc[2][4][4];
#pragma unroll
    for (int mt = 0; mt < 2; mt++)
#pragma unroll
        for (int nt = 0; nt < 4; nt++)
#pragma unroll
            for (int i = 0; i < 4; i++) acc[mt][nt][i] = 0.0f;

    {
#pragma unroll
        for (int i = 0; i < 2; i++) cp16(sbase + aDst[i], A + aOff[i]);
#pragma unroll
        for (int i = 0; i < 4; i++) cp16(sbase + bDst[i], W + bOff[i]);
        asm volatile("cp.async.commit_group;");
    }

    for (int s = 0; s < NSUP; s++) {
        asm volatile("cp.async.wait_group 0;");
        __syncthreads();

        if (s + 1 < NSUP) {
            uint32_t bb = sbase + ((s + 1) & 1) * SBUF_W * 4;
            int off = (s + 1) * 128;
#pragma unroll
            for (int i = 0; i < 2; i++) cp16(bb + aDst[i], A + aOff[i] + off);
#pragma unroll
            for (int i = 0; i < 4; i++) cp16(bb + bDst[i], W + bOff[i] + off);
        }
        asm volatile("cp.async.commit_group;");

        const uint32_t base = sbase + (s & 1) * SBUF_W * 4;
#pragma unroll
        for (int kt = 0; kt < 8; kt++) {
            uint32_t a[2][4];
            ldm_x4(a[0], base + aLaneOff + kt * 32);
            ldm_x4(a[1], base + aLaneOff + 16 * SPITCH * 4 + kt * 32);
#pragma unroll
            for (int q = 0; q < 2; q++) {
                uint32_t b[4];
                ldm_x4(b, base + bLaneOff + q * 16 * SPITCH * 4 + kt * 32);
                mma_f16(acc[0][2 * q],     a[0], b[0], b[2]);
                mma_f16(acc[1][2 * q],     a[1], b[0], b[2]);
                mma_f16(acc[0][2 * q + 1], a[0], b[1], b[3]);
                mma_f16(acc[1][2 * q + 1], a[1], b[1], b[3]);
            }
        }
    }

    const int g = lane >> 2, t = lane & 3;
#pragma unroll
    for (int mt = 0; mt < 2; mt++) {
        int row0 = bm + wm * 32 + mt * 16 + g;
#pragma unroll
        for (int nt = 0; nt < 4; nt++) {
            int col = bn + wn * 32 + nt * 8 + 2 * t;
#pragma unroll
            for (int hrow = 0; hrow < 2; hrow++) {
                int row = row0 + 8 * hrow;
                float v0 = acc[mt][nt][2 * hrow + 0];
                float v1 = acc[mt][nt][2 * hrow + 1];
                if (EPI == 0) {
                    *(float2*)(C + (size_t)row * N + col) = make_float2(v0, v1);
                } else {
                    expand_store(phid, row, col, v0, v1);
                }
            }
        }
    }
}

// ---------------- launch ------------------------------------------------------
extern "C" void kernel_launch(void* const* d_in, const int* in_sizes, int n_in,
                              void* d_out, int out_size) {
    const float* x   = (const float*)d_in[0];
    const float* dw  = (const float*)d_in[1];
    const float* db  = (const float*)d_in[2];
    const float* bw1 = (const float*)d_in[3];
    const float* sw1 = (const float*)d_in[4];
    const float* sc1 = (const float*)d_in[5];
    const float* bw2 = (const float*)d_in[6];
    const float* sw2 = (const float*)d_in[7];
    const float* sc2 = (const float*)d_in[8];
    float* out = (float*)d_out;

    __half *p_phi1, *p_phi2, *p_xh, *p_Wdh, *p_W1, *p_W2;
    cudaGetSymbolAddress((void**)&p_phi1, g_phi1);
    cudaGetSymbolAddress((void**)&p_phi2, g_phi2);
    cudaGetSymbolAddress((void**)&p_xh,   g_xh);
    cudaGetSymbolAddress((void**)&p_Wdh,  g_Wdh);
    cudaGetSymbolAddress((void**)&p_W1,   g_W1);
    cudaGetSymbolAddress((void**)&p_W2,   g_W2);

    cudaFuncSetAttribute(gemm_pre,            cudaFuncAttributeMaxDynamicSharedMemorySize, DSMEM_BYTES);
    cudaFuncSetAttribute(gemm_sup<NSUP_L, 0>, cudaFuncAttributeMaxDynamicSharedMemorySize, SSMEM_BYTES);
    cudaFuncSetAttribute(gemm_sup<NSUP_L, 1>, cudaFuncAttributeMaxDynamicSharedMemorySize, SSMEM_BYTES);

    // launch 0: all prep
    prep_all<<<(N_PREP + 255) / 256, 256>>>(x, dw, bw1, sw1, sc1, bw2, sw2, sc2,
                                            p_xh, p_Wdh, p_W1, p_W2);

    // launch 1: prelude -> phi1 (h0 expanded in epilogue)
    gemm_pre<<<dim3(HID / 256, BATCH / 128), 512, DSMEM_BYTES>>>(p_xh, p_Wdh, db, p_phi1, HID);

    // launch 2: GEMM1 (reads phi1) -> phi2 (h1 expanded in epilogue)
    gemm_sup<NSUP_L, 1><<<dim3(HID / 256, BATCH / 128), 1024, SSMEM_BYTES>>>(
        p_phi1, p_W1, nullptr, p_phi2, HID);

    // launch 3: GEMM2 (reads phi2) -> out
    gemm_sup<NSUP_L, 0><<<dim3(OUTD / 256, BATCH / 128), 1024, SSMEM_BYTES>>>(
        p_phi2, p_W2, out, nullptr, OUTD);
}

// round 16
// speedup vs baseline: 1.0316x; 1.0316x over previous
#include <cuda_runtime.h>
#include <cuda_fp16.h>
#include <math.h>
#include <stdint.h>

#define BATCH   16384
#define LATENT  64
#define HID     512
#define OUTD    256
#define KEXP    (HID * 9)    // 4608 = [silu 512 | bases 4096]
#define NSUP_L  (KEXP / 128) // 36 super-chunks of 128 halves

// ---------------- scratch (device globals; allocation-free rule) ------------
__device__ float  g_h  [(size_t)BATCH * HID];
__device__ __half g_phi[(size_t)BATCH * KEXP];
__device__ __half g_xh [(size_t)BATCH * LATENT];
__device__ __half g_Wdh[(size_t)HID * LATENT];
__device__ __half g_W1 [(size_t)HID  * KEXP];
__device__ __half g_W2 [(size_t)OUTD * KEXP];

// ---------------- helpers -----------------------------------------------------
__device__ __forceinline__ uint32_t smem_u32(const void* p) {
    uint32_t a;
    asm("{ .reg .u64 t; cvta.to.shared.u64 t, %1; cvt.u32.u64 %0, t; }" : "=r"(a) : "l"(p));
    return a;
}
__device__ __forceinline__ void cp16(uint32_t dst, const void* src) {
    asm volatile("cp.async.cg.shared.global [%0], [%1], 16;" :: "r"(dst), "l"(src));
}
__device__ __forceinline__ void ldm_x4(uint32_t* r, uint32_t addr) {
    asm volatile("ldmatrix.sync.aligned.m8n8.x4.shared.b16 {%0,%1,%2,%3}, [%4];"
        : "=r"(r[0]), "=r"(r[1]), "=r"(r[2]), "=r"(r[3]) : "r"(addr));
}
__device__ __forceinline__ void mma_f16(float* d, const uint32_t* a, uint32_t b0, uint32_t b1) {
    asm volatile(
        "mma.sync.aligned.m16n8k16.row.col.f32.f16.f16.f32 "
        "{%0,%1,%2,%3}, {%4,%5,%6,%7}, {%8,%9}, {%0,%1,%2,%3};"
        : "+f"(d[0]), "+f"(d[1]), "+f"(d[2]), "+f"(d[3])
        : "r"(a[0]), "r"(a[1]), "r"(a[2]), "r"(a[3]), "r"(b0), "r"(b1));
}

// ---------------- merged prep kernel ------------------------------------------
#define N_XH   (BATCH * LATENT)
#define N_WDH  (HID * LATENT)
#define N_W1   (HID * HID)
#define N_W2   (OUTD * HID)
#define N_PREP (N_XH + N_WDH + N_W1 + N_W2)

__global__ void prep_all(const float* __restrict__ x, const float* __restrict__ dw,
                         const float* __restrict__ bw1, const float* __restrict__ sw1,
                         const float* __restrict__ sc1,
                         const float* __restrict__ bw2, const float* __restrict__ sw2,
                         const float* __restrict__ sc2,
                         __half* __restrict__ xh, __half* __restrict__ Wdh,
                         __half* __restrict__ W1, __half* __restrict__ W2) {
    int u = blockIdx.x * blockDim.x + threadIdx.x;
    if (u < N_XH) { xh[u] = __float2half_rn(x[u]); return; }
    u -= N_XH;
    if (u < N_WDH) { Wdh[u] = __float2half_rn(dw[u]); return; }
    u -= N_WDH;
    const float* bw; const float* sw; const float* sc; __half* Wt;
    if (u < N_W1) { bw = bw1; sw = sw1; sc = sc1; Wt = W1; }
    else { u -= N_W1; if (u >= N_W2) return; bw = bw2; sw = sw2; sc = sc2; Wt = W2; }
    int o = u / HID, i = u % HID;
    float s = sc[(size_t)o * HID + i];
    Wt[(size_t)o * KEXP + i] = __float2half_rn(bw[(size_t)o * HID + i]);
    size_t base = (size_t)o * KEXP + HID + (size_t)i * 8;
#pragma unroll
    for (int g = 0; g < 8; g++)
        Wt[base + g] = __float2half_rn(sw[((size_t)o * HID + i) * 8 + g] * s);
}

// ---------------- expand: closed-form uniform cubic B-spline ------------------
// Live bases: bas[t0-3..t0] = {(1-u)^3, 3u^3-6u^2+4, -3u^3+3u^2+3u+1, u^3} / 6
__global__ void expand_kernel(const float* __restrict__ h, __half* __restrict__ phi) {
    int idx = blockIdx.x * blockDim.x + threadIdx.x;
    if (idx >= BATCH * HID) return;
    int b = idx / HID, i = idx % HID;
    float xv = h[idx];

    __half* row = phi + (size_t)b * KEXP;
    float si = xv / (1.0f + expf(-xv));
    row[i] = __float2half_rn(si);

    __half* bslot = row + HID + (size_t)i * 8;
    *(uint4*)bslot = make_uint4(0u, 0u, 0u, 0u);

    const float g0 = __fadd_rn(__fmul_rn(-3.0f, 0.4f), -1.0f);
    float s0 = (xv - g0) * 2.5f;
    if (s0 >= 0.0f && s0 < 11.0f) {
        float t0f = floorf(s0);
        int   t0  = (int)t0f;
        float u   = s0 - t0f;
        float um  = 1.0f - u;
        float u2  = u * u, u3 = u2 * u;
        const float c6 = 1.0f / 6.0f;
        __half hv[4];
        hv[0] = __float2half_rn(um * um * um * c6);
        hv[1] = __float2half_rn((3.0f * u3 - 6.0f * u2 + 4.0f) * c6);
        hv[2] = __float2half_rn((-3.0f * u3 + 3.0f * u2 + 3.0f * u + 1.0f) * c6);
        hv[3] = __float2half_rn(u3 * c6);
#pragma unroll
        for (int d = 0; d < 4; d++) {
            int j = t0 - 3 + d;
            if (j >= 0 && j < 8) bslot[j] = hv[d];
        }
    }
}

// ---------------- prelude GEMM (K=64, single chunk; R11-proven) ---------------
#define PITCHW  36
#define DA_W    (128 * PITCHW)
#define DB_W    (256 * PITCHW)
#define DSMEM_BYTES ((DA_W + DB_W) * 4)

__global__ __launch_bounds__(512, 1) void gemm_pre(
    const __half* __restrict__ A, const __half* __restrict__ W,
    const float* __restrict__ bias, float* __restrict__ C, int N)
{
    constexpr int K = LATENT;
    extern __shared__ __align__(16) uint32_t smu[];
    const uint32_t sbase = smem_u32(smu);
    const int tid = threadIdx.x;
    const int wid = tid >> 5, lane = tid & 31;
    const int wm = wid & 3, wn = wid >> 2;
    const int bm = blockIdx.y * 128, bn = blockIdx.x * 256;

    const uint32_t laneRow = lane & 15, laneKB = (lane >> 4) * 16;
    const uint32_t aLaneOff = (wm * 32 + laneRow) * (PITCHW * 4) + laneKB;
    const uint32_t bLaneOff = DA_W * 4 + (wn * 64 + laneRow) * (PITCHW * 4) + laneKB;

    {
        int v0 = tid, v1 = tid + 512;
        int r0 = v0 >> 3, c0 = (v0 & 7) << 3;
        int r1 = v1 >> 3, c1 = (v1 & 7) << 3;
        cp16(sbase + (r0 * PITCHW + (c0 >> 1)) * 4, A + (size_t)(bm + r0) * K + c0);
        cp16(sbase + (r1 * PITCHW + (c1 >> 1)) * 4, A + (size_t)(bm + r1) * K + c1);
#pragma unroll
        for (int i = 0; i < 4; i++) {
            int v = tid + i * 512;
            int r = v >> 3, c = (v & 7) << 3;
            cp16(sbase + (DA_W + r * PITCHW + (c >> 1)) * 4, W + (size_t)(bn + r) * K + c);
        }
        asm volatile("cp.async.commit_group;");
        asm volatile("cp.async.wait_group 0;");
        __syncthreads();
    }

    float acc[2][8][4];
#pragma unroll
    for (int mt = 0; mt < 2; mt++)
#pragma unroll
        for (int nt = 0; nt < 8; nt++)
#pragma unroll
            for (int i = 0; i < 4; i++) acc[mt][nt][i] = 0.0f;

#pragma unroll
    for (int kt = 0; kt < 4; kt++) {
        uint32_t a[2][4], b[4][4];
        ldm_x4(a[0], sbase + aLaneOff + kt * 32);
        ldm_x4(a[1], sbase + aLaneOff + 16 * PITCHW * 4 + kt * 32);
#pragma unroll
        for (int p = 0; p < 4; p++)
            ldm_x4(b[p], sbase + bLaneOff + p * 16 * PITCHW * 4 + kt * 32);
#pragma unroll
        for (int p = 0; p < 4; p++) {
            mma_f16(acc[0][2 * p],     a[0], b[p][0], b[p][2]);
            mma_f16(acc[1][2 * p],     a[1], b[p][0], b[p][2]);
            mma_f16(acc[0][2 * p + 1], a[0], b[p][1], b[p][3]);
            mma_f16(acc[1][2 * p + 1], a[1], b[p][1], b[p][3]);
        }
    }

    const int g = lane >> 2, t = lane & 3;
#pragma unroll
    for (int mt = 0; mt < 2; mt++) {
        int row0 = bm + wm * 32 + mt * 16 + g;
#pragma unroll
        for (int nt = 0; nt < 8; nt++) {
            int col = bn + wn * 64 + nt * 8 + 2 * t;
#pragma unroll
            for (int hrow = 0; hrow < 2; hrow++) {
                int row = row0 + 8 * hrow;
                float v0 = acc[mt][nt][2 * hrow + 0] + bias[col];
                float v1 = acc[mt][nt][2 * hrow + 1] + bias[col + 1];
                v0 = v0 / (1.0f + expf(-v0));
                v1 = v1 / (1.0f + expf(-v1));
                *(float2*)(C + (size_t)row * N + col) = make_float2(v0, v1);
            }
        }
    }
}

// ---------------- main GEMM: 1024 threads, 32 warps, warp tile 32x32 ----------
#define SPITCH  68
#define SA_W    (128 * SPITCH)
#define SB_W    (256 * SPITCH)
#define SBUF_W  (SA_W + SB_W)              // 26112 words
#define SSMEM_BYTES (2 * SBUF_W * 4)       // 208896

template <int NSUP>
__global__ __launch_bounds__(1024, 1) void gemm_sup(
    const __half* __restrict__ A, const __half* __restrict__ W,
    float* __restrict__ C, int N)
{
    constexpr int K = NSUP * 128;
    extern __shared__ __align__(16) uint32_t smu[];
    const uint32_t sbase = smem_u32(smu);

    const int tid  = threadIdx.x;
    const int wid  = tid >> 5, lane = tid & 31;
    const int wm   = wid & 3;
    const int wn   = wid >> 2;
    const int bm   = blockIdx.y * 128;
    const int bn   = blockIdx.x * 256;

    const uint32_t laneRow = lane & 15;
    const uint32_t laneKB  = (lane >> 4) * 16;
    const uint32_t aLaneOff = (wm * 32 + laneRow) * (SPITCH * 4) + laneKB;
    const uint32_t bLaneOff = SA_W * 4 + (wn * 32 + laneRow) * (SPITCH * 4) + laneKB;

    uint32_t aOff[2], aDst[2], bOff[4], bDst[4];
#pragma unroll
    for (int i = 0; i < 2; i++) {
        int v = tid + i * 1024;
        int r = v >> 4, c = (v & 15) << 3;
        aOff[i] = (uint32_t)((bm + r) * K + c);
        aDst[i] = (r * SPITCH + (c >> 1)) * 4;
    }
#pragma unroll
    for (int i = 0; i < 4; i++) {
        int v = tid + i * 1024;
        int r = v >> 4, c = (v & 15) << 3;
        bOff[i] = (uint32_t)((bn + r) * K + c);
        bDst[i] = (SA_W + r * SPITCH + (c >> 1)) * 4;
    }

    float acc[2][4][4];
#pragma unroll
    for (int mt = 0; mt < 2; mt++)
#pragma unroll
        for (int nt = 0; nt < 4; nt++)
#pragma unroll
            for (int i = 0; i < 4; i++) acc[mt][nt][i] = 0.0f;

    {
#pragma unroll
        for (int i = 0; i < 2; i++) cp16(sbase + aDst[i], A + aOff[i]);
#pragma unroll
        for (int i = 0; i < 4; i++) cp16(sbase + bDst[i], W + bOff[i]);
        asm volatile("cp.async.commit_group;");
    }

    for (int s = 0; s < NSUP; s++) {
        asm volatile("cp.async.wait_group 0;");
        __syncthreads();

        if (s + 1 < NSUP) {
            uint32_t bb = sbase + ((s + 1) & 1) * SBUF_W * 4;
            int off = (s + 1) * 128;
#pragma unroll
            for (int i = 0; i < 2; i++) cp16(bb + aDst[i], A + aOff[i] + off);
#pragma unroll
            for (int i = 0; i < 4; i++) cp16(bb + bDst[i], W + bOff[i] + off);
        }
        asm volatile("cp.async.commit_group;");

        const uint32_t base = sbase + (s & 1) * SBUF_W * 4;
#pragma unroll
        for (int kt = 0; kt < 8; kt++) {
            uint32_t a[2][4];
            ldm_x4(a[0], base + aLaneOff + kt * 32);
            ldm_x4(a[1], base + aLaneOff + 16 * SPITCH * 4 + kt * 32);
#pragma unroll
            for (int q = 0; q < 2; q++) {
                uint32_t b[4];
                ldm_x4(b, base + bLaneOff + q * 16 * SPITCH * 4 + kt * 32);
                mma_f16(acc[0][2 * q],     a[0], b[0], b[2]);
                mma_f16(acc[1][2 * q],     a[1], b[0], b[2]);
                mma_f16(acc[0][2 * q + 1], a[0], b[1], b[3]);
                mma_f16(acc[1][2 * q + 1], a[1], b[1], b[3]);
            }
        }
    }

    const int g = lane >> 2, t = lane & 3;
#pragma unroll
    for (int mt = 0; mt < 2; mt++) {
        int row0 = bm + wm * 32 + mt * 16 + g;
#pragma unroll
        for (int nt = 0; nt < 4; nt++) {
            int col = bn + wn * 32 + nt * 8 + 2 * t;
#pragma unroll
            for (int hrow = 0; hrow < 2; hrow++) {
                int row = row0 + 8 * hrow;
                *(float2*)(C + (size_t)row * N + col) =
                    make_float2(acc[mt][nt][2 * hrow + 0], acc[mt][nt][2 * hrow + 1]);
            }
        }
    }
}

// ---------------- launch ------------------------------------------------------
extern "C" void kernel_launch(void* const* d_in, const int* in_sizes, int n_in,
                              void* d_out, int out_size) {
    const float* x   = (const float*)d_in[0];
    const float* dw  = (const float*)d_in[1];
    const float* db  = (const float*)d_in[2];
    const float* bw1 = (const float*)d_in[3];
    const float* sw1 = (const float*)d_in[4];
    const float* sc1 = (const float*)d_in[5];
    const float* bw2 = (const float*)d_in[6];
    const float* sw2 = (const float*)d_in[7];
    const float* sc2 = (const float*)d_in[8];
    float* out = (float*)d_out;

    float  *p_h;
    __half *p_phi, *p_xh, *p_Wdh, *p_W1, *p_W2;
    cudaGetSymbolAddress((void**)&p_h,   g_h);
    cudaGetSymbolAddress((void**)&p_phi, g_phi);
    cudaGetSymbolAddress((void**)&p_xh,  g_xh);
    cudaGetSymbolAddress((void**)&p_Wdh, g_Wdh);
    cudaGetSymbolAddress((void**)&p_W1,  g_W1);
    cudaGetSymbolAddress((void**)&p_W2,  g_W2);

    cudaFuncSetAttribute(gemm_pre,         cudaFuncAttributeMaxDynamicSharedMemorySize, DSMEM_BYTES);
    cudaFuncSetAttribute(gemm_sup<NSUP_L>, cudaFuncAttributeMaxDynamicSharedMemorySize, SSMEM_BYTES);

    // launch 0: all prep (keeps GEMM1 at profiled launch idx 3)
    prep_all<<<(N_PREP + 255) / 256, 256>>>(x, dw, bw1, sw1, sc1, bw2, sw2, sc2,
                                            p_xh, p_Wdh, p_W1, p_W2);

    // launch 1: prelude
    gemm_pre<<<dim3(HID / 256, BATCH / 128), 512, DSMEM_BYTES>>>(p_xh, p_Wdh, db, p_h, HID);

    int expBlocks = (BATCH * HID + 255) / 256;

    // launch 2-3: expand + GEMM1 (profiled)
    expand_kernel<<<expBlocks, 256>>>(p_h, p_phi);
    gemm_sup<NSUP_L><<<dim3(HID / 256, BATCH / 128), 1024, SSMEM_BYTES>>>(p_phi, p_W1, p_h, HID);

    // launch 4-5: expand + GEMM2
    expand_kernel<<<expBlocks, 256>>>(p_h, p_phi);
    gemm_sup<NSUP_L><<<dim3(OUTD / 256, BATCH / 128), 1024, SSMEM_BYTES>>>(p_phi, p_W2, out, OUTD);
}

// round 17
// speedup vs baseline: 1.1577x; 1.1222x over previous
#include <cuda_runtime.h>
#include <cuda_fp16.h>
#include <math.h>
#include <stdint.h>

#define BATCH   16384
#define LATENT  64
#define HID     512
#define OUTD    256
#define KEXP    (HID * 9)    // 4608 = [silu 512 | bases 4096]
#define KCH     64           // K-chunk in halves
#define NCH_L   (KEXP / KCH) // 72

// ---------------- scratch (device globals; allocation-free rule) ------------
__device__ float  g_h  [(size_t)BATCH * HID];
__device__ __half g_phi[(size_t)BATCH * KEXP];
__device__ __half g_xh [(size_t)BATCH * LATENT];
__device__ __half g_Wdh[(size_t)HID * LATENT];
__device__ __half g_W1 [(size_t)HID  * KEXP];
__device__ __half g_W2 [(size_t)OUTD * KEXP];

// ---------------- helpers -----------------------------------------------------
__device__ __forceinline__ uint32_t smem_u32(const void* p) {
    uint32_t a;
    asm("{ .reg .u64 t; cvta.to.shared.u64 t, %1; cvt.u32.u64 %0, t; }" : "=r"(a) : "l"(p));
    return a;
}
__device__ __forceinline__ void cp16(uint32_t dst, const void* src) {
    asm volatile("cp.async.cg.shared.global [%0], [%1], 16;" :: "r"(dst), "l"(src));
}
__device__ __forceinline__ void ldm_x4(uint32_t* r, uint32_t addr) {
    asm volatile("ldmatrix.sync.aligned.m8n8.x4.shared.b16 {%0,%1,%2,%3}, [%4];"
        : "=r"(r[0]), "=r"(r[1]), "=r"(r[2]), "=r"(r[3]) : "r"(addr));
}
__device__ __forceinline__ void mma_f16(float* d, const uint32_t* a, uint32_t b0, uint32_t b1) {
    asm volatile(
        "mma.sync.aligned.m16n8k16.row.col.f32.f16.f16.f32 "
        "{%0,%1,%2,%3}, {%4,%5,%6,%7}, {%8,%9}, {%0,%1,%2,%3};"
        : "+f"(d[0]), "+f"(d[1]), "+f"(d[2]), "+f"(d[3])
        : "r"(a[0]), "r"(a[1]), "r"(a[2]), "r"(a[3]), "r"(b0), "r"(b1));
}
__device__ __forceinline__ float silu_fast(float v) {
    return v / (1.0f + __expf(-v));
}

// ---------------- merged prep kernel ------------------------------------------
#define N_XH   (BATCH * LATENT)
#define N_WDH  (HID * LATENT)
#define N_W1   (HID * HID)
#define N_W2   (OUTD * HID)
#define N_PREP (N_XH + N_WDH + N_W1 + N_W2)

__global__ void prep_all(const float* __restrict__ x, const float* __restrict__ dw,
                         const float* __restrict__ bw1, const float* __restrict__ sw1,
                         const float* __restrict__ sc1,
                         const float* __restrict__ bw2, const float* __restrict__ sw2,
                         const float* __restrict__ sc2,
                         __half* __restrict__ xh, __half* __restrict__ Wdh,
                         __half* __restrict__ W1, __half* __restrict__ W2) {
    int u = blockIdx.x * blockDim.x + threadIdx.x;
    if (u < N_XH) { xh[u] = __float2half_rn(x[u]); return; }
    u -= N_XH;
    if (u < N_WDH) { Wdh[u] = __float2half_rn(dw[u]); return; }
    u -= N_WDH;
    const float* bw; const float* sw; const float* sc; __half* Wt;
    if (u < N_W1) { bw = bw1; sw = sw1; sc = sc1; Wt = W1; }
    else { u -= N_W1; if (u >= N_W2) return; bw = bw2; sw = sw2; sc = sc2; Wt = W2; }
    int o = u / HID, i = u % HID;
    float s = sc[(size_t)o * HID + i];
    Wt[(size_t)o * KEXP + i] = __float2half_rn(bw[(size_t)o * HID + i]);
    size_t base = (size_t)o * KEXP + HID + (size_t)i * 8;
#pragma unroll
    for (int g = 0; g < 8; g++)
        Wt[base + g] = __float2half_rn(sw[((size_t)o * HID + i) * 8 + g] * s);
}

// ---------------- expand: h -> [silu | bases], 2 elems/thread -----------------
// Division-free Cox-de Boor recursion (R11-proven numerics).
__device__ __forceinline__ void bases8_rec(float xv, __half* hb) {
    float g[12];
#pragma unroll
    for (int j = 0; j < 12; j++)
        g[j] = __fadd_rn(__fmul_rn((float)(j - 3), 0.4f), -1.0f);
    float bas[11];
#pragma unroll
    for (int j = 0; j < 11; j++)
        bas[j] = (xv >= g[j] && xv < g[j + 1]) ? 1.0f : 0.0f;
    const float rcp[3] = {2.5f, 1.25f, (float)(1.0 / 1.2)};
#pragma unroll
    for (int k = 1; k <= 3; k++) {
        float r = rcp[k - 1];
#pragma unroll
        for (int j = 0; j < 11 - k; j++) {
            float left  = (xv - g[j])         * r * bas[j];
            float right = (g[j + k + 1] - xv) * r * bas[j + 1];
            bas[j] = left + right;
        }
    }
#pragma unroll
    for (int j = 0; j < 8; j++) hb[j] = __float2half_rn(bas[j]);
}

__global__ void expand_kernel(const float* __restrict__ h, __half* __restrict__ phi) {
    int idx = blockIdx.x * blockDim.x + threadIdx.x;
    if (idx >= BATCH * HID / 2) return;
    const int b = idx / (HID / 2);
    const int i = (idx % (HID / 2)) * 2;

    float2 hv = *(const float2*)(h + (size_t)b * HID + i);
    __half* row = phi + (size_t)b * KEXP;

    // silu pair (one 4-byte store)
    *(__half2*)(row + i) = __floats2half2_rn(silu_fast(hv.x), silu_fast(hv.y));

    // bases: 2 x 8 halves = two adjacent uint4 (32B contiguous per thread)
    __half hb[16];
    bases8_rec(hv.x, hb);
    bases8_rec(hv.y, hb + 8);
    *(uint4*)(row + HID + (size_t)i * 8)     = *(uint4*)hb;
    *(uint4*)(row + HID + (size_t)i * 8 + 8) = *(uint4*)(hb + 8);
}

// ---------------- fp16 mma GEMM (R11-proven): C[M,N] = A[M,K] * W[N,K]^T -------
// Block 128x256, BK=64 halves, 512 threads (16 warps, 4x4), warp tile 32x64.
// 3-stage cp.async, one __syncthreads per chunk, ldmatrix fragments.
#define PITCHW  36
#define A_W     (128 * PITCHW)
#define B_W     (256 * PITCHW)
#define BUF_W   (A_W + B_W)
#define SMEM_BYTES (3 * BUF_W * 4)        // 165888

template <int NCHUNK_T, int EPI>
__global__ __launch_bounds__(512, 1) void gemm_mma(
    const __half* __restrict__ A, const __half* __restrict__ W,
    const float* __restrict__ bias, float* __restrict__ C, int N)
{
    constexpr int K = NCHUNK_T * KCH;
    extern __shared__ __align__(16) uint32_t smu[];
    const uint32_t sbase = smem_u32(smu);

    const int tid  = threadIdx.x;
    const int wid  = tid >> 5, lane = tid & 31;
    const int wm   = wid & 3;
    const int wn   = wid >> 2;
    const int bm   = blockIdx.y * 128;
    const int bn   = blockIdx.x * 256;

    const uint32_t laneRow = lane & 15;
    const uint32_t laneKB  = (lane >> 4) * 16;
    const uint32_t aLaneOff = (wm * 32 + laneRow) * (PITCHW * 4) + laneKB;
    const uint32_t bLaneOff = A_W * 4 + (wn * 64 + laneRow) * (PITCHW * 4) + laneKB;

    const int ar0 = tid >> 3,         ac0 = (tid & 7) << 3;
    const int ar1 = (tid + 512) >> 3, ac1 = ((tid + 512) & 7) << 3;
    const __half* aSrc0 = A + (size_t)(bm + ar0) * K + ac0;
    const __half* aSrc1 = A + (size_t)(bm + ar1) * K + ac1;
    const __half* bSrc[4];
    int bn_[4], bc_[4];
#pragma unroll
    for (int i = 0; i < 4; i++) {
        int v = tid + i * 512;
        bn_[i] = v >> 3; bc_[i] = (v & 7) << 3;
        bSrc[i] = W + (size_t)(bn + bn_[i]) * K + bc_[i];
    }
    const uint32_t aDst0 = (ar0 * PITCHW + (ac0 >> 1)) * 4;
    const uint32_t aDst1 = (ar1 * PITCHW + (ac1 >> 1)) * 4;
    uint32_t bDst[4];
#pragma unroll
    for (int i = 0; i < 4; i++) bDst[i] = (A_W + bn_[i] * PITCHW + (bc_[i] >> 1)) * 4;

    float acc[2][8][4];
#pragma unroll
    for (int mt = 0; mt < 2; mt++)
#pragma unroll
        for (int nt = 0; nt < 8; nt++)
#pragma unroll
            for (int i = 0; i < 4; i++) acc[mt][nt][i] = 0.0f;

#pragma unroll
    for (int c = 0; c < 2; c++) {
        if (c < NCHUNK_T) {
            uint32_t bb = sbase + c * BUF_W * 4;
            cp16(bb + aDst0, aSrc0 + c * KCH);
            cp16(bb + aDst1, aSrc1 + c * KCH);
#pragma unroll
            for (int i = 0; i < 4; i++) cp16(bb + bDst[i], bSrc[i] + c * KCH);
        }
        asm volatile("cp.async.commit_group;");
    }

    int buf = 0;
    for (int c = 0; c < NCHUNK_T; c++) {
        asm volatile("cp.async.wait_group 1;");
        __syncthreads();

        if (c + 2 < NCHUNK_T) {
            int nb = buf + 2; if (nb >= 3) nb -= 3;
            uint32_t bb = sbase + nb * BUF_W * 4;
            int off = (c + 2) * KCH;
            cp16(bb + aDst0, aSrc0 + off);
            cp16(bb + aDst1, aSrc1 + off);
#pragma unroll
            for (int i = 0; i < 4; i++) cp16(bb + bDst[i], bSrc[i] + off);
        }
        asm volatile("cp.async.commit_group;");

        const uint32_t base = sbase + buf * BUF_W * 4;
#pragma unroll
        for (int kt = 0; kt < 4; kt++) {
            uint32_t a[2][4], b[4][4];
            ldm_x4(a[0], base + aLaneOff + kt * 32);
            ldm_x4(a[1], base + aLaneOff + 16 * PITCHW * 4 + kt * 32);
#pragma unroll
            for (int p = 0; p < 4; p++)
                ldm_x4(b[p], base + bLaneOff + p * 16 * PITCHW * 4 + kt * 32);
#pragma unroll
            for (int p = 0; p < 4; p++) {
                mma_f16(acc[0][2 * p],     a[0], b[p][0], b[p][2]);
                mma_f16(acc[1][2 * p],     a[1], b[p][0], b[p][2]);
                mma_f16(acc[0][2 * p + 1], a[0], b[p][1], b[p][3]);
                mma_f16(acc[1][2 * p + 1], a[1], b[p][1], b[p][3]);
            }
        }
        buf++; if (buf == 3) buf = 0;
    }

    const int g = lane >> 2, t = lane & 3;
#pragma unroll
    for (int mt = 0; mt < 2; mt++) {
        int row0 = bm + wm * 32 + mt * 16 + g;
#pragma unroll
        for (int nt = 0; nt < 8; nt++) {
            int col = bn + wn * 64 + nt * 8 + 2 * t;
#pragma unroll
            for (int hrow = 0; hrow < 2; hrow++) {
                int row = row0 + 8 * hrow;
                float v0 = acc[mt][nt][2 * hrow + 0];
                float v1 = acc[mt][nt][2 * hrow + 1];
                if (EPI == 1) {
                    v0 += bias[col];     v1 += bias[col + 1];
                    v0 = silu_fast(v0);
                    v1 = silu_fast(v1);
                }
                *(float2*)(C + (size_t)row * N + col) = make_float2(v0, v1);
            }
        }
    }
}

// ---------------- launch ------------------------------------------------------
extern "C" void kernel_launch(void* const* d_in, const int* in_sizes, int n_in,
                              void* d_out, int out_size) {
    const float* x   = (const float*)d_in[0];
    const float* dw  = (const float*)d_in[1];
    const float* db  = (const float*)d_in[2];
    const float* bw1 = (const float*)d_in[3];
    const float* sw1 = (const float*)d_in[4];
    const float* sc1 = (const float*)d_in[5];
    const float* bw2 = (const float*)d_in[6];
    const float* sw2 = (const float*)d_in[7];
    const float* sc2 = (const float*)d_in[8];
    float* out = (float*)d_out;

    float  *p_h;
    __half *p_phi, *p_xh, *p_Wdh, *p_W1, *p_W2;
    cudaGetSymbolAddress((void**)&p_h,   g_h);
    cudaGetSymbolAddress((void**)&p_phi, g_phi);
    cudaGetSymbolAddress((void**)&p_xh,  g_xh);
    cudaGetSymbolAddress((void**)&p_Wdh, g_Wdh);
    cudaGetSymbolAddress((void**)&p_W1,  g_W1);
    cudaGetSymbolAddress((void**)&p_W2,  g_W2);

    cudaFuncSetAttribute(gemm_mma<NCH_L, 0>, cudaFuncAttributeMaxDynamicSharedMemorySize, SMEM_BYTES);
    cudaFuncSetAttribute(gemm_mma<1, 1>,     cudaFuncAttributeMaxDynamicSharedMemorySize, SMEM_BYTES);

    // launch 0: ALL prep in one kernel (keeps GEMM1 at profiled launch idx 3)
    prep_all<<<(N_PREP + 255) / 256, 256>>>(x, dw, bw1, sw1, sc1, bw2, sw2, sc2,
                                            p_xh, p_Wdh, p_W1, p_W2);

    // launch 1: prelude h0 = silu(x @ dense_w^T + b)
    gemm_mma<1, 1><<<dim3(HID / 256, BATCH / 128), 512, SMEM_BYTES>>>(
        p_xh, p_Wdh, db, p_h, HID);

    int expBlocks = (BATCH * HID / 2 + 255) / 256;

    // launch 2: expand; launch 3: GEMM1 (profiled)
    expand_kernel<<<expBlocks, 256>>>(p_h, p_phi);
    gemm_mma<NCH_L, 0><<<dim3(HID / 256, BATCH / 128), 512, SMEM_BYTES>>>(
        p_phi, p_W1, nullptr, p_h, HID);

    // launch 4: expand; launch 5: GEMM2
    expand_kernel<<<expBlocks, 256>>>(p_h, p_phi);
    gemm_mma<NCH_L, 0><<<dim3(OUTD / 256, BATCH / 128), 512, SMEM_BYTES>>>(
        p_phi, p_W2, nullptr, out, OUTD);
}